// round 1
// baseline (speedup 1.0000x reference)
#include <cuda_runtime.h>
#include <cuda_bf16.h>
#include <cstdint>

// ---------------------------------------------------------------------------
// GCN: 3 layers over N=100000 nodes, E=1.6M edges, self-loops, sym-norm.
// Refactor: hs = (x@W) * dinv[row];  agg[d] = hs[d] + sum_{(s,d) in E} hs[s];
//           out = agg * dinv + b  (+relu for layer 1)
// ---------------------------------------------------------------------------

#define MAXN 100352          // padded node count
#define FDIM 128

__device__ float g_bufA[MAXN * FDIM];
__device__ float g_bufB[MAXN * FDIM];
__device__ float g_bufC[MAXN * FDIM];
__device__ float g_dinv[MAXN];

// ---------------------------------------------------------------------------
// Degree kernels
// ---------------------------------------------------------------------------
__global__ void deg_init_kernel(float* deg, int M) {
    int i = blockIdx.x * blockDim.x + threadIdx.x;
    if (i < M) deg[i] = 1.0f;   // self loop
}

__global__ void deg_accum_kernel(const int* __restrict__ dst, float* deg, int E) {
    int i = blockIdx.x * blockDim.x + threadIdx.x;
    if (i < E) atomicAdd(&deg[dst[i]], 1.0f);
}

__global__ void deg_rsqrt_kernel(float* deg, int M) {
    int i = blockIdx.x * blockDim.x + threadIdx.x;
    if (i < M) deg[i] = rsqrtf(deg[i]);
}

// ---------------------------------------------------------------------------
// SGEMM: C = A[M,128] @ W[128,128], epilogue scales row by dinv[row],
// stores result to BOTH hs and agg (agg init == self-loop contribution).
// BM=BN=128, BK=16, 256 threads, 8x8 per-thread tile.
// ---------------------------------------------------------------------------
__global__ __launch_bounds__(256) void gemm128_kernel(
    const float* __restrict__ A, const float* __restrict__ W,
    const float* __restrict__ dinv,
    float* __restrict__ hs, float* __restrict__ agg, int M)
{
    __shared__ float As[16][128];   // [k][m]
    __shared__ float Bs[16][128];   // [k][n]

    const int block_row = blockIdx.x * 128;
    const int tid = threadIdx.x;
    const int tx = tid & 15;        // 16 across N
    const int ty = tid >> 4;        // 16 across M

    float acc[8][8];
    #pragma unroll
    for (int i = 0; i < 8; i++)
        #pragma unroll
        for (int j = 0; j < 8; j++) acc[i][j] = 0.0f;

    for (int kp = 0; kp < 128; kp += 16) {
        // Load A tile 128x16 (512 float4, 2 per thread), transpose into As[k][m]
        #pragma unroll
        for (int i = 0; i < 2; i++) {
            int idx = tid * 2 + i;          // 0..511
            int ar  = idx >> 2;             // 0..127
            int ac  = (idx & 3) * 4;        // 0,4,8,12
            int grow = block_row + ar;
            float4 v = make_float4(0.f, 0.f, 0.f, 0.f);
            if (grow < M) v = *(const float4*)(A + (size_t)grow * 128 + kp + ac);
            As[ac + 0][ar] = v.x;
            As[ac + 1][ar] = v.y;
            As[ac + 2][ar] = v.z;
            As[ac + 3][ar] = v.w;
        }
        // Load B tile 16x128 (512 float4, 2 per thread)
        #pragma unroll
        for (int i = 0; i < 2; i++) {
            int idx = tid * 2 + i;
            int br  = idx >> 5;             // 0..15
            int bc  = (idx & 31) * 4;       // 0..124
            float4 v = *(const float4*)(W + (size_t)(kp + br) * 128 + bc);
            *(float4*)&Bs[br][bc] = v;
        }
        __syncthreads();

        #pragma unroll
        for (int k = 0; k < 16; k++) {
            float a[8], b[8];
            *(float4*)&a[0] = *(const float4*)&As[k][ty * 8];
            *(float4*)&a[4] = *(const float4*)&As[k][ty * 8 + 4];
            *(float4*)&b[0] = *(const float4*)&Bs[k][tx * 8];
            *(float4*)&b[4] = *(const float4*)&Bs[k][tx * 8 + 4];
            #pragma unroll
            for (int i = 0; i < 8; i++)
                #pragma unroll
                for (int j = 0; j < 8; j++) acc[i][j] += a[i] * b[j];
        }
        __syncthreads();
    }

    #pragma unroll
    for (int i = 0; i < 8; i++) {
        int grow = block_row + ty * 8 + i;
        if (grow >= M) break;
        float s = dinv[grow];
        #pragma unroll
        for (int j = 0; j < 8; j += 4) {
            float4 v;
            v.x = acc[i][j + 0] * s;
            v.y = acc[i][j + 1] * s;
            v.z = acc[i][j + 2] * s;
            v.w = acc[i][j + 3] * s;
            int gcol = tx * 8 + j;
            *(float4*)(hs  + (size_t)grow * 128 + gcol) = v;
            *(float4*)(agg + (size_t)grow * 128 + gcol) = v;
        }
    }
}

// ---------------------------------------------------------------------------
// Edge scatter: one warp per edge. Gather hs[src] (512B coalesced),
// red.global.add.v4.f32 into agg[dst].
// ---------------------------------------------------------------------------
__global__ __launch_bounds__(256) void scatter_kernel(
    const int* __restrict__ src, const int* __restrict__ dst,
    const float* __restrict__ hs, float* __restrict__ agg, int E)
{
    int warp = (blockIdx.x * 256 + threadIdx.x) >> 5;
    int lane = threadIdx.x & 31;
    if (warp >= E) return;
    int s = __ldg(src + warp);
    int d = __ldg(dst + warp);
    float4 v = __ldg((const float4*)(hs + (size_t)s * 128) + lane);
    float* q = agg + (size_t)d * 128 + lane * 4;
    asm volatile("red.global.add.v4.f32 [%0], {%1,%2,%3,%4};"
                 :: "l"(q), "f"(v.x), "f"(v.y), "f"(v.z), "f"(v.w)
                 : "memory");
}

// ---------------------------------------------------------------------------
// Finalize: out = agg * dinv[row] + bias  (optional relu)
// One float4 per thread over M*32 float4s.
// ---------------------------------------------------------------------------
__global__ __launch_bounds__(256) void finalize_kernel(
    const float* __restrict__ agg, const float* __restrict__ dinv,
    const float* __restrict__ bias, float* __restrict__ out, int M, int relu)
{
    int idx = blockIdx.x * blockDim.x + threadIdx.x;
    if (idx >= M * 32) return;
    int row = idx >> 5;
    int c4  = idx & 31;
    float s = dinv[row];
    float4 v = *((const float4*)agg + idx);
    float4 b = *((const float4*)bias + c4);
    v.x = v.x * s + b.x;
    v.y = v.y * s + b.y;
    v.z = v.z * s + b.z;
    v.w = v.w * s + b.w;
    if (relu) {
        v.x = fmaxf(v.x, 0.f); v.y = fmaxf(v.y, 0.f);
        v.z = fmaxf(v.z, 0.f); v.w = fmaxf(v.w, 0.f);
    }
    *((float4*)out + idx) = v;
}

// ---------------------------------------------------------------------------
// Output GEMM: out[M,40] = A[M,128] @ W[128,40] + bias
// block: 64 rows, 128 threads, 4x5 per-thread tile.
// ---------------------------------------------------------------------------
__global__ __launch_bounds__(128) void gemm_out_kernel(
    const float* __restrict__ A, const float* __restrict__ W,
    const float* __restrict__ bias, float* __restrict__ out, int M)
{
    __shared__ float As[128][64];    // [k][r]  32KB
    __shared__ float Ws[128 * 40];   // 20KB

    const int rb  = blockIdx.x * 64;
    const int tid = threadIdx.x;

    for (int i = tid; i < 128 * 40; i += 128) Ws[i] = W[i];

    // load A transposed: 64 rows x 32 float4 = 2048 float4, 16 per thread
    for (int i = tid; i < 64 * 32; i += 128) {
        int r  = i >> 5;
        int c4 = i & 31;
        int grow = rb + r;
        float4 v = make_float4(0.f, 0.f, 0.f, 0.f);
        if (grow < M) v = *(const float4*)(A + (size_t)grow * 128 + c4 * 4);
        As[c4 * 4 + 0][r] = v.x;
        As[c4 * 4 + 1][r] = v.y;
        As[c4 * 4 + 2][r] = v.z;
        As[c4 * 4 + 3][r] = v.w;
    }
    __syncthreads();

    const int tcol = tid & 7;    // 8 groups of 5 cols
    const int trow = tid >> 3;   // 16 groups of 4 rows
    float acc[4][5];
    #pragma unroll
    for (int i = 0; i < 4; i++)
        #pragma unroll
        for (int j = 0; j < 5; j++) acc[i][j] = 0.0f;

    #pragma unroll 4
    for (int k = 0; k < 128; k++) {
        float a[4], w[5];
        #pragma unroll
        for (int i = 0; i < 4; i++) a[i] = As[k][trow * 4 + i];
        #pragma unroll
        for (int j = 0; j < 5; j++) w[j] = Ws[k * 40 + tcol * 5 + j];
        #pragma unroll
        for (int i = 0; i < 4; i++)
            #pragma unroll
            for (int j = 0; j < 5; j++) acc[i][j] += a[i] * w[j];
    }

    #pragma unroll
    for (int i = 0; i < 4; i++) {
        int grow = rb + trow * 4 + i;
        if (grow >= M) break;
        #pragma unroll
        for (int j = 0; j < 5; j++) {
            int c = tcol * 5 + j;
            out[(size_t)grow * 40 + c] = acc[i][j] + bias[c];
        }
    }
}

// ---------------------------------------------------------------------------

extern "C" void kernel_launch(void* const* d_in, const int* in_sizes, int n_in,
                              void* d_out, int out_size)
{
    const float* x    = (const float*)d_in[0];
    const int*   ei   = (const int*)d_in[1];
    const float* W1   = (const float*)d_in[2];
    const float* b1   = (const float*)d_in[3];
    const float* W2   = (const float*)d_in[4];
    const float* b2   = (const float*)d_in[5];
    const float* Wout = (const float*)d_in[6];
    const float* bout = (const float*)d_in[7];
    float* out = (float*)d_out;

    const int M = in_sizes[0] / FDIM;
    const int E = in_sizes[1] / 2;
    const int* src = ei;
    const int* dst = ei + E;

    float *bufA, *bufB, *bufC, *dinv;
    cudaGetSymbolAddress((void**)&bufA, g_bufA);
    cudaGetSymbolAddress((void**)&bufB, g_bufB);
    cudaGetSymbolAddress((void**)&bufC, g_bufC);
    cudaGetSymbolAddress((void**)&dinv, g_dinv);

    const int nb_nodes = (M + 255) / 256;
    const int nb_edges = (E + 255) / 256;
    const int nb_scat  = (int)(((long long)E * 32 + 255) / 256);
    const int nb_gemm  = (M + 127) / 128;
    const int nb_fin   = (M * 32 + 255) / 256;
    const int nb_gout  = (M + 63) / 64;

    // degrees -> dinv
    deg_init_kernel<<<nb_nodes, 256>>>(dinv, M);
    deg_accum_kernel<<<nb_edges, 256>>>(dst, dinv, E);
    deg_rsqrt_kernel<<<nb_nodes, 256>>>(dinv, M);

    // Layer 1: hs1 -> bufA, agg1 -> bufB
    gemm128_kernel<<<nb_gemm, 256>>>(x, W1, dinv, bufA, bufB, M);
    scatter_kernel<<<nb_scat, 256>>>(src, dst, bufA, bufB, E);
    finalize_kernel<<<nb_fin, 256>>>(bufB, dinv, b1, bufA, M, 1);   // h1 -> bufA

    // Layer 2: hs2 -> bufB, agg2 -> bufC
    gemm128_kernel<<<nb_gemm, 256>>>(bufA, W2, dinv, bufB, bufC, M);
    scatter_kernel<<<nb_scat, 256>>>(src, dst, bufB, bufC, E);
    finalize_kernel<<<nb_fin, 256>>>(bufC, dinv, b2, bufA, M, 0);   // h2 -> bufA

    // Output projection
    gemm_out_kernel<<<nb_gout, 128>>>(bufA, Wout, bout, out, M);
}

// round 2
// speedup vs baseline: 1.5945x; 1.5945x over previous
#include <cuda_runtime.h>
#include <cuda_bf16.h>
#include <cstdint>

// ---------------------------------------------------------------------------
// GCN: 3 layers, N=100000 nodes, E=1.6M edges, self-loops, sym-norm.
//   hs = (in @ W) * dinv[row]          (in = x, or relu(agg*dinv+b) fused)
//   agg[d] = hs[d] + sum_{(s,d) in E} hs[s]    (atomic-free via CSR-by-dst)
//   out = agg*dinv + b (+relu)         (fused into next GEMM's A-load)
// ---------------------------------------------------------------------------

#define MAXN 100352
#define MAXE 1700000
#define FDIM 128

__device__ float g_bufA[MAXN * FDIM];
__device__ float g_bufB[MAXN * FDIM];
__device__ float g_dinv[MAXN];
__device__ int   g_deg[MAXN];
__device__ int   g_cursor[MAXN];
__device__ int   g_rowptr[MAXN];
__device__ int   g_bsum[256];
__device__ int   g_srcsorted[MAXE];

// ---------------------------------------------------------------------------
// CSR construction
// ---------------------------------------------------------------------------
__global__ void zero_kernel(int* deg, int* cursor, int M) {
    int i = blockIdx.x * blockDim.x + threadIdx.x;
    if (i < M) { deg[i] = 0; cursor[i] = 0; }
}

__global__ void deg_count_kernel(const int* __restrict__ dst, int* deg, int E) {
    int i = blockIdx.x * blockDim.x + threadIdx.x;
    if (i < E) atomicAdd(&deg[dst[i]], 1);
}

__global__ void dinv_kernel(const int* __restrict__ deg, float* dinv, int M) {
    int i = blockIdx.x * blockDim.x + threadIdx.x;
    if (i < M) dinv[i] = rsqrtf((float)deg[i] + 1.0f);   // +1 self loop
}

// block-level exclusive scan over 1024-element chunks
__global__ __launch_bounds__(1024) void scan_block_kernel(
    const int* __restrict__ deg, int* row_ptr, int* bsum, int M)
{
    int gid  = blockIdx.x * 1024 + threadIdx.x;
    int lane = threadIdx.x & 31;
    int wid  = threadIdx.x >> 5;
    int v = (gid < M) ? deg[gid] : 0;
    int x = v;
    #pragma unroll
    for (int o = 1; o < 32; o <<= 1) {
        int t = __shfl_up_sync(0xffffffffu, x, o);
        if (lane >= o) x += t;
    }
    __shared__ int ws[32];
    if (lane == 31) ws[wid] = x;
    __syncthreads();
    if (wid == 0) {
        int y = ws[lane];
        #pragma unroll
        for (int o = 1; o < 32; o <<= 1) {
            int t = __shfl_up_sync(0xffffffffu, y, o);
            if (lane >= o) y += t;
        }
        ws[lane] = y;
    }
    __syncthreads();
    int base = (wid > 0) ? ws[wid - 1] : 0;
    int incl = base + x;
    if (gid < M) row_ptr[gid] = incl - v;
    if (threadIdx.x == 1023) bsum[blockIdx.x] = incl;
}

__global__ void scan_sums_kernel(int* bsum, int nb) {
    if (threadIdx.x == 0 && blockIdx.x == 0) {
        int acc = 0;
        for (int i = 0; i < nb; i++) { int t = bsum[i]; bsum[i] = acc; acc += t; }
    }
}

__global__ void add_offsets_kernel(int* row_ptr, const int* __restrict__ bsum, int M) {
    int gid = blockIdx.x * blockDim.x + threadIdx.x;
    if (gid < M) row_ptr[gid] += bsum[gid >> 10];
}

__global__ void bin_edges_kernel(const int* __restrict__ src, const int* __restrict__ dst,
                                 const int* __restrict__ row_ptr, int* cursor,
                                 int* sorted_src, int E)
{
    int i = blockIdx.x * blockDim.x + threadIdx.x;
    if (i >= E) return;
    int d = dst[i];
    int pos = row_ptr[d] + atomicAdd(&cursor[d], 1);
    sorted_src[pos] = src[i];
}

// ---------------------------------------------------------------------------
// SGEMM: hs = transform(A) @ W, epilogue scales row by dinv[row].
// transform(A) = relu?(A*dinv[row] + bias[col]) if bias != nullptr else A.
// BM=BN=128, BK=16, 256 threads, 8x8 per-thread tile.
// ---------------------------------------------------------------------------
__global__ __launch_bounds__(256) void gemm128_kernel(
    const float* __restrict__ A, const float* __restrict__ W,
    const float* __restrict__ dinv, const float* __restrict__ bias, int relu,
    float* __restrict__ hs, int M)
{
    __shared__ float As[16][128];   // [k][m]
    __shared__ float Bs[16][128];   // [k][n]

    const int block_row = blockIdx.x * 128;
    const int tid = threadIdx.x;
    const int tx = tid & 15;
    const int ty = tid >> 4;

    float acc[8][8];
    #pragma unroll
    for (int i = 0; i < 8; i++)
        #pragma unroll
        for (int j = 0; j < 8; j++) acc[i][j] = 0.0f;

    for (int kp = 0; kp < 128; kp += 16) {
        #pragma unroll
        for (int i = 0; i < 2; i++) {
            int idx = tid * 2 + i;
            int ar  = idx >> 2;
            int ac  = (idx & 3) * 4;
            int grow = block_row + ar;
            float4 v = make_float4(0.f, 0.f, 0.f, 0.f);
            if (grow < M) {
                v = *(const float4*)(A + (size_t)grow * 128 + kp + ac);
                if (bias) {
                    float s = __ldg(dinv + grow);
                    float4 bb = *(const float4*)(bias + kp + ac);
                    v.x = v.x * s + bb.x; v.y = v.y * s + bb.y;
                    v.z = v.z * s + bb.z; v.w = v.w * s + bb.w;
                    if (relu) {
                        v.x = fmaxf(v.x, 0.f); v.y = fmaxf(v.y, 0.f);
                        v.z = fmaxf(v.z, 0.f); v.w = fmaxf(v.w, 0.f);
                    }
                }
            }
            As[ac + 0][ar] = v.x;
            As[ac + 1][ar] = v.y;
            As[ac + 2][ar] = v.z;
            As[ac + 3][ar] = v.w;
        }
        #pragma unroll
        for (int i = 0; i < 2; i++) {
            int idx = tid * 2 + i;
            int br  = idx >> 5;
            int bc  = (idx & 31) * 4;
            float4 v = *(const float4*)(W + (size_t)(kp + br) * 128 + bc);
            *(float4*)&Bs[br][bc] = v;
        }
        __syncthreads();

        #pragma unroll
        for (int k = 0; k < 16; k++) {
            float a[8], b[8];
            *(float4*)&a[0] = *(const float4*)&As[k][ty * 8];
            *(float4*)&a[4] = *(const float4*)&As[k][ty * 8 + 4];
            *(float4*)&b[0] = *(const float4*)&Bs[k][tx * 8];
            *(float4*)&b[4] = *(const float4*)&Bs[k][tx * 8 + 4];
            #pragma unroll
            for (int i = 0; i < 8; i++)
                #pragma unroll
                for (int j = 0; j < 8; j++) acc[i][j] += a[i] * b[j];
        }
        __syncthreads();
    }

    #pragma unroll
    for (int i = 0; i < 8; i++) {
        int grow = block_row + ty * 8 + i;
        if (grow >= M) break;
        float s = __ldg(dinv + grow);
        #pragma unroll
        for (int j = 0; j < 8; j += 4) {
            float4 v;
            v.x = acc[i][j + 0] * s;
            v.y = acc[i][j + 1] * s;
            v.z = acc[i][j + 2] * s;
            v.w = acc[i][j + 3] * s;
            *(float4*)(hs + (size_t)grow * 128 + tx * 8 + j) = v;
        }
    }
}

// ---------------------------------------------------------------------------
// Atomic-free aggregation: one warp per dst node.
//   agg[v] = hs[v] + sum_{s in CSR[v]} hs[s]
// ---------------------------------------------------------------------------
__global__ __launch_bounds__(256) void agg_kernel(
    const int* __restrict__ sorted_src, const int* __restrict__ row_ptr,
    const int* __restrict__ deg,
    const float* __restrict__ hs, float* __restrict__ agg, int M)
{
    int node = (blockIdx.x * 256 + threadIdx.x) >> 5;
    int lane = threadIdx.x & 31;
    if (node >= M) return;

    int beg = __ldg(row_ptr + node);
    int cnt = __ldg(deg + node);

    float4 acc = __ldg((const float4*)(hs + (size_t)node * 128) + lane);

    int e = 0;
    while (e < cnt) {
        int batch = min(32, cnt - e);
        int s = (lane < batch) ? __ldg(sorted_src + beg + e + lane) : 0;
        int j = 0;
        for (; j + 4 <= batch; j += 4) {
            int s0 = __shfl_sync(0xffffffffu, s, j + 0);
            int s1 = __shfl_sync(0xffffffffu, s, j + 1);
            int s2 = __shfl_sync(0xffffffffu, s, j + 2);
            int s3 = __shfl_sync(0xffffffffu, s, j + 3);
            float4 v0 = __ldg((const float4*)(hs + (size_t)s0 * 128) + lane);
            float4 v1 = __ldg((const float4*)(hs + (size_t)s1 * 128) + lane);
            float4 v2 = __ldg((const float4*)(hs + (size_t)s2 * 128) + lane);
            float4 v3 = __ldg((const float4*)(hs + (size_t)s3 * 128) + lane);
            acc.x += v0.x + v1.x + v2.x + v3.x;
            acc.y += v0.y + v1.y + v2.y + v3.y;
            acc.z += v0.z + v1.z + v2.z + v3.z;
            acc.w += v0.w + v1.w + v2.w + v3.w;
        }
        for (; j < batch; j++) {
            int sj = __shfl_sync(0xffffffffu, s, j);
            float4 v = __ldg((const float4*)(hs + (size_t)sj * 128) + lane);
            acc.x += v.x; acc.y += v.y; acc.z += v.z; acc.w += v.w;
        }
        e += batch;
    }

    *((float4*)(agg + (size_t)node * 128) + lane) = acc;
}

// ---------------------------------------------------------------------------
// Output GEMM: out[M,40] = transform(A) @ Wout + bout
// transform(A) = A*dinv[row] + b2[col]  (layer-2 finalize fused, no relu)
// ---------------------------------------------------------------------------
__global__ __launch_bounds__(128) void gemm_out_kernel(
    const float* __restrict__ A, const float* __restrict__ W,
    const float* __restrict__ dinv, const float* __restrict__ bias2,
    const float* __restrict__ bout, float* __restrict__ out, int M)
{
    __shared__ float As[128][64];    // [k][r]
    __shared__ float Ws[128 * 40];

    const int rb  = blockIdx.x * 64;
    const int tid = threadIdx.x;

    for (int i = tid; i < 128 * 40; i += 128) Ws[i] = W[i];

    for (int i = tid; i < 64 * 32; i += 128) {
        int r  = i >> 5;
        int c4 = i & 31;
        int grow = rb + r;
        float4 v = make_float4(0.f, 0.f, 0.f, 0.f);
        if (grow < M) {
            v = *(const float4*)(A + (size_t)grow * 128 + c4 * 4);
            float s = __ldg(dinv + grow);
            float4 bb = *(const float4*)(bias2 + c4 * 4);
            v.x = v.x * s + bb.x; v.y = v.y * s + bb.y;
            v.z = v.z * s + bb.z; v.w = v.w * s + bb.w;
        }
        As[c4 * 4 + 0][r] = v.x;
        As[c4 * 4 + 1][r] = v.y;
        As[c4 * 4 + 2][r] = v.z;
        As[c4 * 4 + 3][r] = v.w;
    }
    __syncthreads();

    const int tcol = tid & 7;
    const int trow = tid >> 3;
    float acc[4][5];
    #pragma unroll
    for (int i = 0; i < 4; i++)
        #pragma unroll
        for (int j = 0; j < 5; j++) acc[i][j] = 0.0f;

    #pragma unroll 4
    for (int k = 0; k < 128; k++) {
        float a[4], w[5];
        #pragma unroll
        for (int i = 0; i < 4; i++) a[i] = As[k][trow * 4 + i];
        #pragma unroll
        for (int j = 0; j < 5; j++) w[j] = Ws[k * 40 + tcol * 5 + j];
        #pragma unroll
        for (int i = 0; i < 4; i++)
            #pragma unroll
            for (int j = 0; j < 5; j++) acc[i][j] += a[i] * w[j];
    }

    #pragma unroll
    for (int i = 0; i < 4; i++) {
        int grow = rb + trow * 4 + i;
        if (grow >= M) break;
        #pragma unroll
        for (int j = 0; j < 5; j++) {
            int c = tcol * 5 + j;
            out[(size_t)grow * 40 + c] = acc[i][j] + __ldg(bout + c);
        }
    }
}

// ---------------------------------------------------------------------------

extern "C" void kernel_launch(void* const* d_in, const int* in_sizes, int n_in,
                              void* d_out, int out_size)
{
    const float* x    = (const float*)d_in[0];
    const int*   ei   = (const int*)d_in[1];
    const float* W1   = (const float*)d_in[2];
    const float* b1   = (const float*)d_in[3];
    const float* W2   = (const float*)d_in[4];
    const float* b2   = (const float*)d_in[5];
    const float* Wout = (const float*)d_in[6];
    const float* bout = (const float*)d_in[7];
    float* out = (float*)d_out;

    const int M = in_sizes[0] / FDIM;
    const int E = in_sizes[1] / 2;
    const int* src = ei;
    const int* dst = ei + E;

    float *bufA, *bufB, *dinv;
    int *deg, *cursor, *rowptr, *bsum, *srcsorted;
    cudaGetSymbolAddress((void**)&bufA, g_bufA);
    cudaGetSymbolAddress((void**)&bufB, g_bufB);
    cudaGetSymbolAddress((void**)&dinv, g_dinv);
    cudaGetSymbolAddress((void**)&deg, g_deg);
    cudaGetSymbolAddress((void**)&cursor, g_cursor);
    cudaGetSymbolAddress((void**)&rowptr, g_rowptr);
    cudaGetSymbolAddress((void**)&bsum, g_bsum);
    cudaGetSymbolAddress((void**)&srcsorted, g_srcsorted);

    const int nb_nodes = (M + 255) / 256;
    const int nb_edges = (E + 255) / 256;
    const int nb_scan  = (M + 1023) / 1024;
    const int nb_gemm  = (M + 127) / 128;
    const int nb_agg   = (M + 7) / 8;          // 8 warps per 256-thread block
    const int nb_gout  = (M + 63) / 64;

    // --- CSR build + dinv ---
    zero_kernel<<<nb_nodes, 256>>>(deg, cursor, M);
    deg_count_kernel<<<nb_edges, 256>>>(dst, deg, E);
    dinv_kernel<<<nb_nodes, 256>>>(deg, dinv, M);
    scan_block_kernel<<<nb_scan, 1024>>>(deg, rowptr, bsum, M);
    scan_sums_kernel<<<1, 32>>>(bsum, nb_scan);
    add_offsets_kernel<<<nb_nodes, 256>>>(rowptr, bsum, M);
    bin_edges_kernel<<<nb_edges, 256>>>(src, dst, rowptr, cursor, srcsorted, E);

    // --- Layer 1: hs1 -> bufA; agg1 -> bufB ---
    gemm128_kernel<<<nb_gemm, 256>>>(x, W1, dinv, nullptr, 0, bufA, M);
    agg_kernel<<<nb_agg, 256>>>(srcsorted, rowptr, deg, bufA, bufB, M);

    // --- Layer 2: h1 = relu(agg1*dinv + b1) fused into A-load; hs2 -> bufA ---
    gemm128_kernel<<<nb_gemm, 256>>>(bufB, W2, dinv, b1, 1, bufA, M);
    agg_kernel<<<nb_agg, 256>>>(srcsorted, rowptr, deg, bufA, bufB, M);

    // --- Output: h2 = agg2*dinv + b2 fused; out = h2 @ Wout + bout ---
    gemm_out_kernel<<<nb_gout, 128>>>(bufB, Wout, dinv, b2, bout, out, M);
}

// round 3
// speedup vs baseline: 1.7700x; 1.1101x over previous
#include <cuda_runtime.h>
#include <cuda_bf16.h>
#include <cstdint>

// ---------------------------------------------------------------------------
// GCN: 3 layers, N=100000, E=1.6M, self-loops, sym-norm.
//   hs = (in @ W) * dinv[row]      in = x  or  relu(agg*dinv+b) (fused in A-load)
//   agg[d] = hs[d] + sum_{(s,d)} hs[s]    (atomic-free CSR-by-dst gather)
//   GEMM 128x128 via split-tf32 mma.sync (3-term, fp32-class accuracy)
// ---------------------------------------------------------------------------

#define MAXN 100352
#define MAXE 1700000
#define FDIM 128

__device__ float g_bufA[MAXN * FDIM];
__device__ float g_bufB[MAXN * FDIM];
__device__ float g_dinv[MAXN];
__device__ int   g_deg[MAXN];
__device__ int   g_cursor[MAXN];
__device__ int   g_rowptr[MAXN];
__device__ int   g_bsum[256];
__device__ int   g_srcsorted[MAXE];
// W fragments (tf32 hi/lo), frag order: [na(16)][ka(16)][lane(32)][reg(2)]
__device__ float g_W1hi[16384];
__device__ float g_W1lo[16384];
__device__ float g_W2hi[16384];
__device__ float g_W2lo[16384];

// ---------------------------------------------------------------------------
__device__ __forceinline__ unsigned tf32_of(float x) {
    unsigned r;
    asm("cvt.rna.tf32.f32 %0, %1;" : "=r"(r) : "f"(x));
    return r;
}

__device__ __forceinline__ void mma_tf32(float* d, const unsigned* a, const unsigned* b) {
    asm volatile(
        "mma.sync.aligned.m16n8k8.row.col.f32.tf32.tf32.f32 "
        "{%0,%1,%2,%3}, {%4,%5,%6,%7}, {%8,%9}, {%0,%1,%2,%3};\n"
        : "+f"(d[0]), "+f"(d[1]), "+f"(d[2]), "+f"(d[3])
        : "r"(a[0]), "r"(a[1]), "r"(a[2]), "r"(a[3]), "r"(b[0]), "r"(b[1]));
}

// ---------------------------------------------------------------------------
// CSR construction
// ---------------------------------------------------------------------------
__global__ void zero_kernel(int* deg, int* cursor, int M) {
    int i = blockIdx.x * blockDim.x + threadIdx.x;
    if (i < M) { deg[i] = 0; cursor[i] = 0; }
}

__global__ void deg_count_kernel(const int* __restrict__ dst, int* deg, int E) {
    int i = blockIdx.x * blockDim.x + threadIdx.x;
    if (i < E) atomicAdd(&deg[dst[i]], 1);
}

__global__ void dinv_kernel(const int* __restrict__ deg, float* dinv, int M) {
    int i = blockIdx.x * blockDim.x + threadIdx.x;
    if (i < M) dinv[i] = rsqrtf((float)deg[i] + 1.0f);
}

__global__ __launch_bounds__(1024) void scan_block_kernel(
    const int* __restrict__ deg, int* row_ptr, int* bsum, int M)
{
    int gid  = blockIdx.x * 1024 + threadIdx.x;
    int lane = threadIdx.x & 31;
    int wid  = threadIdx.x >> 5;
    int v = (gid < M) ? deg[gid] : 0;
    int x = v;
    #pragma unroll
    for (int o = 1; o < 32; o <<= 1) {
        int t = __shfl_up_sync(0xffffffffu, x, o);
        if (lane >= o) x += t;
    }
    __shared__ int ws[32];
    if (lane == 31) ws[wid] = x;
    __syncthreads();
    if (wid == 0) {
        int y = ws[lane];
        #pragma unroll
        for (int o = 1; o < 32; o <<= 1) {
            int t = __shfl_up_sync(0xffffffffu, y, o);
            if (lane >= o) y += t;
        }
        ws[lane] = y;
    }
    __syncthreads();
    int base = (wid > 0) ? ws[wid - 1] : 0;
    int incl = base + x;
    if (gid < M) row_ptr[gid] = incl - v;
    if (threadIdx.x == 1023) bsum[blockIdx.x] = incl;
}

__global__ void scan_sums_kernel(int* bsum, int nb) {
    if (threadIdx.x == 0 && blockIdx.x == 0) {
        int acc = 0;
        for (int i = 0; i < nb; i++) { int t = bsum[i]; bsum[i] = acc; acc += t; }
    }
}

__global__ void add_offsets_kernel(int* row_ptr, const int* __restrict__ bsum, int M) {
    int gid = blockIdx.x * blockDim.x + threadIdx.x;
    if (gid < M) row_ptr[gid] += bsum[gid >> 10];
}

__global__ void bin_edges_kernel(const int* __restrict__ src, const int* __restrict__ dst,
                                 const int* __restrict__ row_ptr, int* cursor,
                                 int* sorted_src, int E)
{
    int i = blockIdx.x * blockDim.x + threadIdx.x;
    if (i >= E) return;
    int d = dst[i];
    int pos = row_ptr[d] + atomicAdd(&cursor[d], 1);
    sorted_src[pos] = src[i];
}

// ---------------------------------------------------------------------------
// W fragment prep: scatter W[128][128] into mma b-frag order, split tf32 hi/lo.
// element (k,n): na=n>>3, gb=n&7, ka=k>>3, cb=k&3, reg=(k>>2)&1, lane=gb*4+cb
// ---------------------------------------------------------------------------
__global__ void wprep_kernel(const float* __restrict__ W, float* hi, float* lo) {
    int idx = blockIdx.x * blockDim.x + threadIdx.x;   // 0..16383
    if (idx >= 16384) return;
    int k = idx >> 7;
    int n = idx & 127;
    float w = W[idx];
    unsigned h = tf32_of(w);
    float hf = __uint_as_float(h);
    unsigned l = tf32_of(w - hf);
    int na = n >> 3, gb = n & 7;
    int ka = k >> 3, cb = k & 3, reg = (k >> 2) & 1;
    int lane = gb * 4 + cb;
    int off = ((na * 16 + ka) * 32 + lane) * 2 + reg;
    hi[off] = __uint_as_float(h);
    lo[off] = __uint_as_float(l);
}

// ---------------------------------------------------------------------------
// Tensor-core GEMM: hs = transform(A)[M,128] @ W[128,128], row-scaled by dinv.
// Block 128 rows, 8 warps, warp grid 4(M)x2(N), warp tile 32x64.
// A staged in smem in fragment order; W frags streamed from gmem (L1-resident).
// Split-tf32: acc += Ahi*Bhi + Alo*Bhi + Ahi*Blo.
// ---------------------------------------------------------------------------
__global__ __launch_bounds__(256, 2) void gemm_tc_kernel(
    const float* __restrict__ A,
    const float* __restrict__ Whi, const float* __restrict__ Wlo,
    const float* __restrict__ dinv, const float* __restrict__ bias, int relu,
    float* __restrict__ hs, int M)
{
    extern __shared__ float As[];   // 8*16*32*4 = 16384 floats = 64KB

    const int tid  = threadIdx.x;
    const int lane = tid & 31;
    const int warp = tid >> 5;
    const int block_row = blockIdx.x * 128;

    // ---- load A tile (128x128) into fragment-order smem ----
    #pragma unroll
    for (int it = 0; it < 16; it++) {
        int idx = it * 256 + tid;          // 0..4095
        int m  = idx >> 5;                 // row in tile
        int kq = idx & 31;                 // float4 index along K
        int grow = block_row + m;
        float4 v = make_float4(0.f, 0.f, 0.f, 0.f);
        if (grow < M) {
            v = *(const float4*)(A + (size_t)grow * 128 + kq * 4);
            if (bias) {
                float s = __ldg(dinv + grow);
                float4 bb = *(const float4*)(bias + kq * 4);
                v.x = v.x * s + bb.x; v.y = v.y * s + bb.y;
                v.z = v.z * s + bb.z; v.w = v.w * s + bb.w;
                if (relu) {
                    v.x = fmaxf(v.x, 0.f); v.y = fmaxf(v.y, 0.f);
                    v.z = fmaxf(v.z, 0.f); v.w = fmaxf(v.w, 0.f);
                }
            }
        }
        float vv[4] = {v.x, v.y, v.z, v.w};
        int g  = m & 7;
        int hi = (m >> 3) & 1;
        int ma = m >> 4;
        int ka = kq >> 1;
        int ch = kq & 1;
        int reg = hi + 2 * ch;
        int base = (ma * 16 + ka) * 32 * 4;
        #pragma unroll
        for (int j = 0; j < 4; j++) {
            int c = (j + tid) & 3;                       // rotation: spread banks
            int lane_s = ((g * 4 + c) + ka * 4) & 31;    // per-ka lane rotation
            As[base + lane_s * 4 + reg] = vv[c];
        }
    }
    __syncthreads();

    // ---- mainloop ----
    const int warp_m = warp >> 1;     // 0..3
    const int warp_n = warp & 1;      // 0..1

    float acc[2][8][4];
    #pragma unroll
    for (int i = 0; i < 2; i++)
        #pragma unroll
        for (int j = 0; j < 8; j++)
            #pragma unroll
            for (int r = 0; r < 4; r++) acc[i][j][r] = 0.0f;

    #pragma unroll
    for (int ka = 0; ka < 16; ka++) {
        unsigned ah[2][4], al[2][4];
        int lane_s = (lane + ka * 4) & 31;
        #pragma unroll
        for (int i = 0; i < 2; i++) {
            int ma = warp_m * 2 + i;
            const float4 av = *(const float4*)(As + ((ma * 16 + ka) * 32 + lane_s) * 4);
            float f;
            ah[i][0] = tf32_of(av.x); f = __uint_as_float(ah[i][0]); al[i][0] = tf32_of(av.x - f);
            ah[i][1] = tf32_of(av.y); f = __uint_as_float(ah[i][1]); al[i][1] = tf32_of(av.y - f);
            ah[i][2] = tf32_of(av.z); f = __uint_as_float(ah[i][2]); al[i][2] = tf32_of(av.z - f);
            ah[i][3] = tf32_of(av.w); f = __uint_as_float(ah[i][3]); al[i][3] = tf32_of(av.w - f);
        }
        #pragma unroll
        for (int j = 0; j < 8; j++) {
            int na = warp_n * 8 + j;
            size_t off = ((size_t)(na * 16 + ka) * 32 + lane) * 2;
            float2 bh2 = __ldg((const float2*)(Whi + off));
            float2 bl2 = __ldg((const float2*)(Wlo + off));
            unsigned bh[2] = {__float_as_uint(bh2.x), __float_as_uint(bh2.y)};
            unsigned bl[2] = {__float_as_uint(bl2.x), __float_as_uint(bl2.y)};
            #pragma unroll
            for (int i = 0; i < 2; i++) {
                mma_tf32(acc[i][j], ah[i], bh);
                mma_tf32(acc[i][j], al[i], bh);
                mma_tf32(acc[i][j], ah[i], bl);
            }
        }
    }

    // ---- epilogue: scale rows by dinv, store ----
    int g  = lane >> 2;
    int qc = lane & 3;
    #pragma unroll
    for (int i = 0; i < 2; i++) {
        int r0 = block_row + warp_m * 32 + i * 16 + g;
        int r1 = r0 + 8;
        float s0 = (r0 < M) ? __ldg(dinv + r0) : 0.f;
        float s1 = (r1 < M) ? __ldg(dinv + r1) : 0.f;
        #pragma unroll
        for (int j = 0; j < 8; j++) {
            int col = warp_n * 64 + j * 8 + qc * 2;
            if (r0 < M) {
                float2 v = make_float2(acc[i][j][0] * s0, acc[i][j][1] * s0);
                *(float2*)(hs + (size_t)r0 * 128 + col) = v;
            }
            if (r1 < M) {
                float2 v = make_float2(acc[i][j][2] * s1, acc[i][j][3] * s1);
                *(float2*)(hs + (size_t)r1 * 128 + col) = v;
            }
        }
    }
}

// ---------------------------------------------------------------------------
// Atomic-free aggregation: one warp per dst node.
// ---------------------------------------------------------------------------
__global__ __launch_bounds__(256) void agg_kernel(
    const int* __restrict__ sorted_src, const int* __restrict__ row_ptr,
    const int* __restrict__ deg,
    const float* __restrict__ hs, float* __restrict__ agg, int M)
{
    int node = (blockIdx.x * 256 + threadIdx.x) >> 5;
    int lane = threadIdx.x & 31;
    if (node >= M) return;

    int beg = __ldg(row_ptr + node);
    int cnt = __ldg(deg + node);

    float4 acc = __ldg((const float4*)(hs + (size_t)node * 128) + lane);

    int e = 0;
    while (e < cnt) {
        int batch = min(32, cnt - e);
        int s = (lane < batch) ? __ldg(sorted_src + beg + e + lane) : 0;
        int j = 0;
        for (; j + 4 <= batch; j += 4) {
            int s0 = __shfl_sync(0xffffffffu, s, j + 0);
            int s1 = __shfl_sync(0xffffffffu, s, j + 1);
            int s2 = __shfl_sync(0xffffffffu, s, j + 2);
            int s3 = __shfl_sync(0xffffffffu, s, j + 3);
            float4 v0 = __ldg((const float4*)(hs + (size_t)s0 * 128) + lane);
            float4 v1 = __ldg((const float4*)(hs + (size_t)s1 * 128) + lane);
            float4 v2 = __ldg((const float4*)(hs + (size_t)s2 * 128) + lane);
            float4 v3 = __ldg((const float4*)(hs + (size_t)s3 * 128) + lane);
            acc.x += v0.x + v1.x + v2.x + v3.x;
            acc.y += v0.y + v1.y + v2.y + v3.y;
            acc.z += v0.z + v1.z + v2.z + v3.z;
            acc.w += v0.w + v1.w + v2.w + v3.w;
        }
        for (; j < batch; j++) {
            int sj = __shfl_sync(0xffffffffu, s, j);
            float4 v = __ldg((const float4*)(hs + (size_t)sj * 128) + lane);
            acc.x += v.x; acc.y += v.y; acc.z += v.z; acc.w += v.w;
        }
        e += batch;
    }

    *((float4*)(agg + (size_t)node * 128) + lane) = acc;
}

// ---------------------------------------------------------------------------
// Output GEMM: out[M,40] = (A*dinv + b2) @ Wout + bout
// ---------------------------------------------------------------------------
__global__ __launch_bounds__(128) void gemm_out_kernel(
    const float* __restrict__ A, const float* __restrict__ W,
    const float* __restrict__ dinv, const float* __restrict__ bias2,
    const float* __restrict__ bout, float* __restrict__ out, int M)
{
    __shared__ float As2[128][64];
    __shared__ float Ws[128 * 40];

    const int rb  = blockIdx.x * 64;
    const int tid = threadIdx.x;

    for (int i = tid; i < 128 * 40; i += 128) Ws[i] = W[i];

    for (int i = tid; i < 64 * 32; i += 128) {
        int r  = i >> 5;
        int c4 = i & 31;
        int grow = rb + r;
        float4 v = make_float4(0.f, 0.f, 0.f, 0.f);
        if (grow < M) {
            v = *(const float4*)(A + (size_t)grow * 128 + c4 * 4);
            float s = __ldg(dinv + grow);
            float4 bb = *(const float4*)(bias2 + c4 * 4);
            v.x = v.x * s + bb.x; v.y = v.y * s + bb.y;
            v.z = v.z * s + bb.z; v.w = v.w * s + bb.w;
        }
        As2[c4 * 4 + 0][r] = v.x;
        As2[c4 * 4 + 1][r] = v.y;
        As2[c4 * 4 + 2][r] = v.z;
        As2[c4 * 4 + 3][r] = v.w;
    }
    __syncthreads();

    const int tcol = tid & 7;
    const int trow = tid >> 3;
    float acc[4][5];
    #pragma unroll
    for (int i = 0; i < 4; i++)
        #pragma unroll
        for (int j = 0; j < 5; j++) acc[i][j] = 0.0f;

    #pragma unroll 4
    for (int k = 0; k < 128; k++) {
        float a[4], w[5];
        #pragma unroll
        for (int i = 0; i < 4; i++) a[i] = As2[k][trow * 4 + i];
        #pragma unroll
        for (int j = 0; j < 5; j++) w[j] = Ws[k * 40 + tcol * 5 + j];
        #pragma unroll
        for (int i = 0; i < 4; i++)
            #pragma unroll
            for (int j = 0; j < 5; j++) acc[i][j] += a[i] * w[j];
    }

    #pragma unroll
    for (int i = 0; i < 4; i++) {
        int grow = rb + trow * 4 + i;
        if (grow >= M) break;
        #pragma unroll
        for (int j = 0; j < 5; j++) {
            int c = tcol * 5 + j;
            out[(size_t)grow * 40 + c] = acc[i][j] + __ldg(bout + c);
        }
    }
}

// ---------------------------------------------------------------------------

extern "C" void kernel_launch(void* const* d_in, const int* in_sizes, int n_in,
                              void* d_out, int out_size)
{
    const float* x    = (const float*)d_in[0];
    const int*   ei   = (const int*)d_in[1];
    const float* W1   = (const float*)d_in[2];
    const float* b1   = (const float*)d_in[3];
    const float* W2   = (const float*)d_in[4];
    const float* b2   = (const float*)d_in[5];
    const float* Wout = (const float*)d_in[6];
    const float* bout = (const float*)d_in[7];
    float* out = (float*)d_out;

    const int M = in_sizes[0] / FDIM;
    const int E = in_sizes[1] / 2;
    const int* src = ei;
    const int* dst = ei + E;

    float *bufA, *bufB, *dinv, *w1hi, *w1lo, *w2hi, *w2lo;
    int *deg, *cursor, *rowptr, *bsum, *srcsorted;
    cudaGetSymbolAddress((void**)&bufA, g_bufA);
    cudaGetSymbolAddress((void**)&bufB, g_bufB);
    cudaGetSymbolAddress((void**)&dinv, g_dinv);
    cudaGetSymbolAddress((void**)&deg, g_deg);
    cudaGetSymbolAddress((void**)&cursor, g_cursor);
    cudaGetSymbolAddress((void**)&rowptr, g_rowptr);
    cudaGetSymbolAddress((void**)&bsum, g_bsum);
    cudaGetSymbolAddress((void**)&srcsorted, g_srcsorted);
    cudaGetSymbolAddress((void**)&w1hi, g_W1hi);
    cudaGetSymbolAddress((void**)&w1lo, g_W1lo);
    cudaGetSymbolAddress((void**)&w2hi, g_W2hi);
    cudaGetSymbolAddress((void**)&w2lo, g_W2lo);

    static int smem_set = 0;
    if (!smem_set) {
        cudaFuncSetAttribute(gemm_tc_kernel,
                             cudaFuncAttributeMaxDynamicSharedMemorySize, 65536);
        smem_set = 1;
    }

    const int nb_nodes = (M + 255) / 256;
    const int nb_edges = (E + 255) / 256;
    const int nb_scan  = (M + 1023) / 1024;
    const int nb_gemm  = (M + 127) / 128;
    const int nb_agg   = (M + 7) / 8;
    const int nb_gout  = (M + 63) / 64;

    // --- W fragment prep + CSR build + dinv ---
    wprep_kernel<<<64, 256>>>(W1, w1hi, w1lo);
    wprep_kernel<<<64, 256>>>(W2, w2hi, w2lo);
    zero_kernel<<<nb_nodes, 256>>>(deg, cursor, M);
    deg_count_kernel<<<nb_edges, 256>>>(dst, deg, E);
    dinv_kernel<<<nb_nodes, 256>>>(deg, dinv, M);
    scan_block_kernel<<<nb_scan, 1024>>>(deg, rowptr, bsum, M);
    scan_sums_kernel<<<1, 32>>>(bsum, nb_scan);
    add_offsets_kernel<<<nb_nodes, 256>>>(rowptr, bsum, M);
    bin_edges_kernel<<<nb_edges, 256>>>(src, dst, rowptr, cursor, srcsorted, E);

    // --- Layer 1: hs1 -> bufA; agg1 -> bufB ---
    gemm_tc_kernel<<<nb_gemm, 256, 65536>>>(x, w1hi, w1lo, dinv, nullptr, 0, bufA, M);
    agg_kernel<<<nb_agg, 256>>>(srcsorted, rowptr, deg, bufA, bufB, M);

    // --- Layer 2: relu(agg1*dinv+b1) fused into A-load; hs2 -> bufA ---
    gemm_tc_kernel<<<nb_gemm, 256, 65536>>>(bufB, w2hi, w2lo, dinv, b1, 1, bufA, M);
    agg_kernel<<<nb_agg, 256>>>(srcsorted, rowptr, deg, bufA, bufB, M);

    // --- Output: h2 = agg2*dinv + b2 fused; out = h2 @ Wout + bout ---
    gemm_out_kernel<<<nb_gout, 128>>>(bufB, Wout, dinv, b2, bout, out, M);
}

// round 4
// speedup vs baseline: 1.9996x; 1.1297x over previous
#include <cuda_runtime.h>
#include <cuda_bf16.h>
#include <cuda_fp16.h>
#include <cstdint>

// ---------------------------------------------------------------------------
// GCN: 3 layers, N=100000, E=1.6M, self-loops, sym-norm.
//   hs = (in @ W) * dinv[row]   (fp16 storage; in = x or relu(agg*dinv+b) fused)
//   agg[d] = hs[d] + sum_{(s,d)} hs[s]    (atomic-free CSR-by-dst gather, fp32 acc)
//   GEMM 128x128 via split-tf32 mma.sync (3-term, fp32-class accuracy)
// ---------------------------------------------------------------------------

#define MAXN 100352
#define MAXE 1700000
#define FDIM 128

__device__ __half g_bufH[MAXN * FDIM];   // hs (fp16)
__device__ float  g_bufB[MAXN * FDIM];   // agg (fp32)
__device__ float  g_dinv[MAXN];
__device__ int    g_deg[MAXN];
__device__ int    g_cursor[MAXN];
__device__ int    g_rowptr[MAXN];
__device__ int    g_bsum[256];
__device__ int    g_srcsorted[MAXE];
// W fragments (tf32 hi/lo), frag order: [na(16)][ka(16)][lane(32)][reg(2)]
__device__ float g_W1hi[16384];
__device__ float g_W1lo[16384];
__device__ float g_W2hi[16384];
__device__ float g_W2lo[16384];

// ---------------------------------------------------------------------------
__device__ __forceinline__ unsigned tf32_of(float x) {
    unsigned r;
    asm("cvt.rna.tf32.f32 %0, %1;" : "=r"(r) : "f"(x));
    return r;
}

__device__ __forceinline__ void mma_tf32(float* d, const unsigned* a, const unsigned* b) {
    asm volatile(
        "mma.sync.aligned.m16n8k8.row.col.f32.tf32.tf32.f32 "
        "{%0,%1,%2,%3}, {%4,%5,%6,%7}, {%8,%9}, {%0,%1,%2,%3};\n"
        : "+f"(d[0]), "+f"(d[1]), "+f"(d[2]), "+f"(d[3])
        : "r"(a[0]), "r"(a[1]), "r"(a[2]), "r"(a[3]), "r"(b[0]), "r"(b[1]));
}

// ---------------------------------------------------------------------------
// CSR construction
// ---------------------------------------------------------------------------
__global__ void zero_kernel(int* deg, int M) {
    int i = blockIdx.x * blockDim.x + threadIdx.x;
    if (i < M) deg[i] = 0;
}

__global__ void deg_count_kernel(const int* __restrict__ dst, int* deg, int E) {
    int i = (blockIdx.x * blockDim.x + threadIdx.x) * 4;
    if (i + 3 < E) {
        int4 d = *(const int4*)(dst + i);
        atomicAdd(&deg[d.x], 1);
        atomicAdd(&deg[d.y], 1);
        atomicAdd(&deg[d.z], 1);
        atomicAdd(&deg[d.w], 1);
    } else {
        for (int j = i; j < E; j++) atomicAdd(&deg[dst[j]], 1);
    }
}

__global__ void dinv_kernel(const int* __restrict__ deg, float* dinv, int M) {
    int i = blockIdx.x * blockDim.x + threadIdx.x;
    if (i < M) dinv[i] = rsqrtf((float)deg[i] + 1.0f);
}

__global__ __launch_bounds__(1024) void scan_block_kernel(
    const int* __restrict__ deg, int* row_ptr, int* bsum, int M)
{
    int gid  = blockIdx.x * 1024 + threadIdx.x;
    int lane = threadIdx.x & 31;
    int wid  = threadIdx.x >> 5;
    int v = (gid < M) ? deg[gid] : 0;
    int x = v;
    #pragma unroll
    for (int o = 1; o < 32; o <<= 1) {
        int t = __shfl_up_sync(0xffffffffu, x, o);
        if (lane >= o) x += t;
    }
    __shared__ int ws[32];
    if (lane == 31) ws[wid] = x;
    __syncthreads();
    if (wid == 0) {
        int y = ws[lane];
        #pragma unroll
        for (int o = 1; o < 32; o <<= 1) {
            int t = __shfl_up_sync(0xffffffffu, y, o);
            if (lane >= o) y += t;
        }
        ws[lane] = y;
    }
    __syncthreads();
    int base = (wid > 0) ? ws[wid - 1] : 0;
    int incl = base + x;
    if (gid < M) row_ptr[gid] = incl - v;
    if (threadIdx.x == 1023) bsum[blockIdx.x] = incl;
}

__global__ void scan_sums_kernel(int* bsum, int nb) {
    if (threadIdx.x == 0 && blockIdx.x == 0) {
        int acc = 0;
        for (int i = 0; i < nb; i++) { int t = bsum[i]; bsum[i] = acc; acc += t; }
    }
}

__global__ void add_offsets_kernel(int* row_ptr, int* cursor,
                                   const int* __restrict__ bsum, int M) {
    int gid = blockIdx.x * blockDim.x + threadIdx.x;
    if (gid < M) {
        int v = row_ptr[gid] + bsum[gid >> 10];
        row_ptr[gid] = v;
        cursor[gid]  = v;
    }
}

__global__ void bin_edges_kernel(const int* __restrict__ src, const int* __restrict__ dst,
                                 int* cursor, int* sorted_src, int E)
{
    int i = blockIdx.x * blockDim.x + threadIdx.x;
    if (i >= E) return;
    int pos = atomicAdd(&cursor[dst[i]], 1);
    sorted_src[pos] = src[i];
}

// ---------------------------------------------------------------------------
// W fragment prep: scatter W[128][128] into mma b-frag order, split tf32 hi/lo.
// ---------------------------------------------------------------------------
__global__ void wprep_kernel(const float* __restrict__ W, float* hi, float* lo) {
    int idx = blockIdx.x * blockDim.x + threadIdx.x;
    if (idx >= 16384) return;
    int k = idx >> 7;
    int n = idx & 127;
    float w = W[idx];
    unsigned h = tf32_of(w);
    float hf = __uint_as_float(h);
    unsigned l = tf32_of(w - hf);
    int na = n >> 3, gb = n & 7;
    int ka = k >> 3, cb = k & 3, reg = (k >> 2) & 1;
    int lane = gb * 4 + cb;
    int off = ((na * 16 + ka) * 32 + lane) * 2 + reg;
    hi[off] = __uint_as_float(h);
    lo[off] = __uint_as_float(l);
}

// ---------------------------------------------------------------------------
// Tensor-core GEMM: hs(half) = transform(A)[M,128] @ W[128,128], row-scaled.
// Block 128 rows, 8 warps, warp grid 4(M)x2(N), warp tile 32x64.
// ---------------------------------------------------------------------------
__global__ __launch_bounds__(256, 2) void gemm_tc_kernel(
    const float* __restrict__ A,
    const float* __restrict__ Whi, const float* __restrict__ Wlo,
    const float* __restrict__ dinv, const float* __restrict__ bias, int relu,
    __half* __restrict__ hs, int M)
{
    extern __shared__ float As[];   // 16384 floats = 64KB

    const int tid  = threadIdx.x;
    const int lane = tid & 31;
    const int warp = tid >> 5;
    const int block_row = blockIdx.x * 128;

    // ---- load A tile into fragment-order smem ----
    #pragma unroll
    for (int it = 0; it < 16; it++) {
        int idx = it * 256 + tid;
        int m  = idx >> 5;
        int kq = idx & 31;
        int grow = block_row + m;
        float4 v = make_float4(0.f, 0.f, 0.f, 0.f);
        if (grow < M) {
            v = *(const float4*)(A + (size_t)grow * 128 + kq * 4);
            if (bias) {
                float s = __ldg(dinv + grow);
                float4 bb = *(const float4*)(bias + kq * 4);
                v.x = v.x * s + bb.x; v.y = v.y * s + bb.y;
                v.z = v.z * s + bb.z; v.w = v.w * s + bb.w;
                if (relu) {
                    v.x = fmaxf(v.x, 0.f); v.y = fmaxf(v.y, 0.f);
                    v.z = fmaxf(v.z, 0.f); v.w = fmaxf(v.w, 0.f);
                }
            }
        }
        float vv[4] = {v.x, v.y, v.z, v.w};
        int g  = m & 7;
        int hi = (m >> 3) & 1;
        int ma = m >> 4;
        int ka = kq >> 1;
        int ch = kq & 1;
        int reg = hi + 2 * ch;
        int base = (ma * 16 + ka) * 32 * 4;
        #pragma unroll
        for (int j = 0; j < 4; j++) {
            int c = (j + tid) & 3;
            int lane_s = ((g * 4 + c) + ka * 4) & 31;
            As[base + lane_s * 4 + reg] = vv[c];
        }
    }
    __syncthreads();

    // ---- mainloop ----
    const int warp_m = warp >> 1;
    const int warp_n = warp & 1;

    float acc[2][8][4];
    #pragma unroll
    for (int i = 0; i < 2; i++)
        #pragma unroll
        for (int j = 0; j < 8; j++)
            #pragma unroll
            for (int r = 0; r < 4; r++) acc[i][j][r] = 0.0f;

    #pragma unroll
    for (int ka = 0; ka < 16; ka++) {
        unsigned ah[2][4], al[2][4];
        int lane_s = (lane + ka * 4) & 31;
        #pragma unroll
        for (int i = 0; i < 2; i++) {
            int ma = warp_m * 2 + i;
            const float4 av = *(const float4*)(As + ((ma * 16 + ka) * 32 + lane_s) * 4);
            float f;
            ah[i][0] = tf32_of(av.x); f = __uint_as_float(ah[i][0]); al[i][0] = tf32_of(av.x - f);
            ah[i][1] = tf32_of(av.y); f = __uint_as_float(ah[i][1]); al[i][1] = tf32_of(av.y - f);
            ah[i][2] = tf32_of(av.z); f = __uint_as_float(ah[i][2]); al[i][2] = tf32_of(av.z - f);
            ah[i][3] = tf32_of(av.w); f = __uint_as_float(ah[i][3]); al[i][3] = tf32_of(av.w - f);
        }
        #pragma unroll
        for (int j = 0; j < 8; j++) {
            int na = warp_n * 8 + j;
            size_t off = ((size_t)(na * 16 + ka) * 32 + lane) * 2;
            float2 bh2 = __ldg((const float2*)(Whi + off));
            float2 bl2 = __ldg((const float2*)(Wlo + off));
            unsigned bh[2] = {__float_as_uint(bh2.x), __float_as_uint(bh2.y)};
            unsigned bl[2] = {__float_as_uint(bl2.x), __float_as_uint(bl2.y)};
            #pragma unroll
            for (int i = 0; i < 2; i++) {
                mma_tf32(acc[i][j], ah[i], bh);
                mma_tf32(acc[i][j], al[i], bh);
                mma_tf32(acc[i][j], ah[i], bl);
            }
        }
    }

    // ---- epilogue: scale rows by dinv, store fp16 ----
    int g  = lane >> 2;
    int qc = lane & 3;
    #pragma unroll
    for (int i = 0; i < 2; i++) {
        int r0 = block_row + warp_m * 32 + i * 16 + g;
        int r1 = r0 + 8;
        float s0 = (r0 < M) ? __ldg(dinv + r0) : 0.f;
        float s1 = (r1 < M) ? __ldg(dinv + r1) : 0.f;
        #pragma unroll
        for (int j = 0; j < 8; j++) {
            int col = warp_n * 64 + j * 8 + qc * 2;
            if (r0 < M)
                *(__half2*)(hs + (size_t)r0 * 128 + col) =
                    __floats2half2_rn(acc[i][j][0] * s0, acc[i][j][1] * s0);
            if (r1 < M)
                *(__half2*)(hs + (size_t)r1 * 128 + col) =
                    __floats2half2_rn(acc[i][j][2] * s1, acc[i][j][3] * s1);
        }
    }
}

// ---------------------------------------------------------------------------
// Atomic-free aggregation: one warp per dst node, fp16 gather, fp32 accumulate.
// Row = 128 halves = 256B; lane covers halves [lane*4, lane*4+4) via uint2.
// ---------------------------------------------------------------------------
__global__ __launch_bounds__(256) void agg_kernel(
    const int* __restrict__ sorted_src, const int* __restrict__ row_ptr,
    const int* __restrict__ deg,
    const __half* __restrict__ hs, float* __restrict__ agg, int M)
{
    int node = (blockIdx.x * 256 + threadIdx.x) >> 5;
    int lane = threadIdx.x & 31;
    if (node >= M) return;

    int beg = __ldg(row_ptr + node);
    int cnt = __ldg(deg + node);

    const uint2* hsrow = (const uint2*)hs;   // 32 uint2 per row

    float4 acc;
    {
        uint2 v = __ldg(hsrow + (size_t)node * 32 + lane);
        float2 a = __half22float2(*(__half2*)&v.x);
        float2 b = __half22float2(*(__half2*)&v.y);
        acc = make_float4(a.x, a.y, b.x, b.y);
    }

    int e = 0;
    while (e < cnt) {
        int batch = min(32, cnt - e);
        int s = (lane < batch) ? __ldg(sorted_src + beg + e + lane) : 0;
        int j = 0;
        for (; j + 4 <= batch; j += 4) {
            int s0 = __shfl_sync(0xffffffffu, s, j + 0);
            int s1 = __shfl_sync(0xffffffffu, s, j + 1);
            int s2 = __shfl_sync(0xffffffffu, s, j + 2);
            int s3 = __shfl_sync(0xffffffffu, s, j + 3);
            uint2 v0 = __ldg(hsrow + (size_t)s0 * 32 + lane);
            uint2 v1 = __ldg(hsrow + (size_t)s1 * 32 + lane);
            uint2 v2 = __ldg(hsrow + (size_t)s2 * 32 + lane);
            uint2 v3 = __ldg(hsrow + (size_t)s3 * 32 + lane);
            float2 a0 = __half22float2(*(__half2*)&v0.x), b0 = __half22float2(*(__half2*)&v0.y);
            float2 a1 = __half22float2(*(__half2*)&v1.x), b1 = __half22float2(*(__half2*)&v1.y);
            float2 a2 = __half22float2(*(__half2*)&v2.x), b2 = __half22float2(*(__half2*)&v2.y);
            float2 a3 = __half22float2(*(__half2*)&v3.x), b3 = __half22float2(*(__half2*)&v3.y);
            acc.x += a0.x + a1.x + a2.x + a3.x;
            acc.y += a0.y + a1.y + a2.y + a3.y;
            acc.z += b0.x + b1.x + b2.x + b3.x;
            acc.w += b0.y + b1.y + b2.y + b3.y;
        }
        for (; j < batch; j++) {
            int sj = __shfl_sync(0xffffffffu, s, j);
            uint2 v = __ldg(hsrow + (size_t)sj * 32 + lane);
            float2 a = __half22float2(*(__half2*)&v.x);
            float2 b = __half22float2(*(__half2*)&v.y);
            acc.x += a.x; acc.y += a.y; acc.z += b.x; acc.w += b.y;
        }
        e += batch;
    }

    *((float4*)(agg + (size_t)node * 128) + lane) = acc;
}

// ---------------------------------------------------------------------------
// Output GEMM: out[M,40] = (A*dinv + b2) @ Wout + bout
// ---------------------------------------------------------------------------
__global__ __launch_bounds__(128) void gemm_out_kernel(
    const float* __restrict__ A, const float* __restrict__ W,
    const float* __restrict__ dinv, const float* __restrict__ bias2,
    const float* __restrict__ bout, float* __restrict__ out, int M)
{
    __shared__ float As2[128][64];
    __shared__ float Ws[128 * 40];

    const int rb  = blockIdx.x * 64;
    const int tid = threadIdx.x;

    for (int i = tid; i < 128 * 40; i += 128) Ws[i] = W[i];

    for (int i = tid; i < 64 * 32; i += 128) {
        int r  = i >> 5;
        int c4 = i & 31;
        int grow = rb + r;
        float4 v = make_float4(0.f, 0.f, 0.f, 0.f);
        if (grow < M) {
            v = *(const float4*)(A + (size_t)grow * 128 + c4 * 4);
            float s = __ldg(dinv + grow);
            float4 bb = *(const float4*)(bias2 + c4 * 4);
            v.x = v.x * s + bb.x; v.y = v.y * s + bb.y;
            v.z = v.z * s + bb.z; v.w = v.w * s + bb.w;
        }
        As2[c4 * 4 + 0][r] = v.x;
        As2[c4 * 4 + 1][r] = v.y;
        As2[c4 * 4 + 2][r] = v.z;
        As2[c4 * 4 + 3][r] = v.w;
    }
    __syncthreads();

    const int tcol = tid & 7;
    const int trow = tid >> 3;
    float acc[4][5];
    #pragma unroll
    for (int i = 0; i < 4; i++)
        #pragma unroll
        for (int j = 0; j < 5; j++) acc[i][j] = 0.0f;

    #pragma unroll 4
    for (int k = 0; k < 128; k++) {
        float a[4], w[5];
        #pragma unroll
        for (int i = 0; i < 4; i++) a[i] = As2[k][trow * 4 + i];
        #pragma unroll
        for (int j = 0; j < 5; j++) w[j] = Ws[k * 40 + tcol * 5 + j];
        #pragma unroll
        for (int i = 0; i < 4; i++)
            #pragma unroll
            for (int j = 0; j < 5; j++) acc[i][j] += a[i] * w[j];
    }

    #pragma unroll
    for (int i = 0; i < 4; i++) {
        int grow = rb + trow * 4 + i;
        if (grow >= M) break;
        #pragma unroll
        for (int j = 0; j < 5; j++) {
            int c = tcol * 5 + j;
            out[(size_t)grow * 40 + c] = acc[i][j] + __ldg(bout + c);
        }
    }
}

// ---------------------------------------------------------------------------

extern "C" void kernel_launch(void* const* d_in, const int* in_sizes, int n_in,
                              void* d_out, int out_size)
{
    const float* x    = (const float*)d_in[0];
    const int*   ei   = (const int*)d_in[1];
    const float* W1   = (const float*)d_in[2];
    const float* b1   = (const float*)d_in[3];
    const float* W2   = (const float*)d_in[4];
    const float* b2   = (const float*)d_in[5];
    const float* Wout = (const float*)d_in[6];
    const float* bout = (const float*)d_in[7];
    float* out = (float*)d_out;

    const int M = in_sizes[0] / FDIM;
    const int E = in_sizes[1] / 2;
    const int* src = ei;
    const int* dst = ei + E;

    __half* bufH;
    float *bufB, *dinv, *w1hi, *w1lo, *w2hi, *w2lo;
    int *deg, *cursor, *rowptr, *bsum, *srcsorted;
    cudaGetSymbolAddress((void**)&bufH, g_bufH);
    cudaGetSymbolAddress((void**)&bufB, g_bufB);
    cudaGetSymbolAddress((void**)&dinv, g_dinv);
    cudaGetSymbolAddress((void**)&deg, g_deg);
    cudaGetSymbolAddress((void**)&cursor, g_cursor);
    cudaGetSymbolAddress((void**)&rowptr, g_rowptr);
    cudaGetSymbolAddress((void**)&bsum, g_bsum);
    cudaGetSymbolAddress((void**)&srcsorted, g_srcsorted);
    cudaGetSymbolAddress((void**)&w1hi, g_W1hi);
    cudaGetSymbolAddress((void**)&w1lo, g_W1lo);
    cudaGetSymbolAddress((void**)&w2hi, g_W2hi);
    cudaGetSymbolAddress((void**)&w2lo, g_W2lo);

    static int smem_set = 0;
    if (!smem_set) {
        cudaFuncSetAttribute(gemm_tc_kernel,
                             cudaFuncAttributeMaxDynamicSharedMemorySize, 65536);
        smem_set = 1;
    }

    const int nb_nodes = (M + 255) / 256;
    const int nb_edges = (E + 255) / 256;
    const int nb_edge4 = (E + 1023) / 1024;
    const int nb_scan  = (M + 1023) / 1024;
    const int nb_gemm  = (M + 127) / 128;
    const int nb_agg   = (M + 7) / 8;
    const int nb_gout  = (M + 63) / 64;

    // --- W fragment prep + CSR build + dinv ---
    wprep_kernel<<<64, 256>>>(W1, w1hi, w1lo);
    wprep_kernel<<<64, 256>>>(W2, w2hi, w2lo);
    zero_kernel<<<nb_nodes, 256>>>(deg, M);
    deg_count_kernel<<<nb_edge4, 256>>>(dst, deg, E);
    dinv_kernel<<<nb_nodes, 256>>>(deg, dinv, M);
    scan_block_kernel<<<nb_scan, 1024>>>(deg, rowptr, bsum, M);
    scan_sums_kernel<<<1, 32>>>(bsum, nb_scan);
    add_offsets_kernel<<<nb_nodes, 256>>>(rowptr, cursor, bsum, M);
    bin_edges_kernel<<<nb_edges, 256>>>(src, dst, cursor, srcsorted, E);

    // --- Layer 1: hs1 -> bufH (fp16); agg1 -> bufB (fp32) ---
    gemm_tc_kernel<<<nb_gemm, 256, 65536>>>(x, w1hi, w1lo, dinv, nullptr, 0, bufH, M);
    agg_kernel<<<nb_agg, 256>>>(srcsorted, rowptr, deg, bufH, bufB, M);

    // --- Layer 2: relu(agg1*dinv+b1) fused into A-load; hs2 -> bufH ---
    gemm_tc_kernel<<<nb_gemm, 256, 65536>>>(bufB, w2hi, w2lo, dinv, b1, 1, bufH, M);
    agg_kernel<<<nb_agg, 256>>>(srcsorted, rowptr, deg, bufH, bufB, M);

    // --- Output: h2 = agg2*dinv + b2 fused; out = h2 @ Wout + bout ---
    gemm_out_kernel<<<nb_gout, 128>>>(bufB, Wout, dinv, b2, bout, out, M);
}

// round 6
// speedup vs baseline: 2.4584x; 1.2295x over previous
#include <cuda_runtime.h>
#include <cuda_bf16.h>
#include <cuda_fp16.h>
#include <cstdint>

// ---------------------------------------------------------------------------
// GCN: 3 layers, N=100000, E=1.6M, self-loops, sym-norm.
//   hs = (in @ W) * dinv[row]   (fp16 storage; in = x or relu(agg*dinv+b) fused)
//   agg[d] = hs[d] + sum_{(s,d)} hs[s]    (atomic-free CSR-by-dst gather, fp32 acc)
//   GEMM 128x128 via fp16 mma.m16n8k16, fp32 accumulate
// ---------------------------------------------------------------------------

#define MAXN 100352
#define MAXE 1700000
#define FDIM 128

__device__ __half g_bufH[MAXN * FDIM];   // hs (fp16)
__device__ float  g_bufB[MAXN * FDIM];   // agg (fp32)
__device__ float  g_dinv[MAXN];
__device__ int    g_deg[MAXN];
__device__ int    g_cursor[MAXN];
__device__ int    g_rowptr[MAXN];
__device__ int    g_bsum[256];
__device__ int    g_srcsorted[MAXE];
// W fp16 b-fragments: [na(16)][kb(8)][lane(32)][reg(2)] of uint(=half2)
__device__ unsigned g_W1f[8192];
__device__ unsigned g_W2f[8192];

// ---------------------------------------------------------------------------
__device__ __forceinline__ unsigned pack_half2(float x, float y) {
    __half2 h = __floats2half2_rn(x, y);
    unsigned u;
    asm("mov.b32 %0, %1;" : "=r"(u) : "r"(*(unsigned*)&h));
    return u;
}

__device__ __forceinline__ void mma_f16(float* d, const unsigned* a, const unsigned* b) {
    asm volatile(
        "mma.sync.aligned.m16n8k16.row.col.f32.f16.f16.f32 "
        "{%0,%1,%2,%3}, {%4,%5,%6,%7}, {%8,%9}, {%0,%1,%2,%3};\n"
        : "+f"(d[0]), "+f"(d[1]), "+f"(d[2]), "+f"(d[3])
        : "r"(a[0]), "r"(a[1]), "r"(a[2]), "r"(a[3]), "r"(b[0]), "r"(b[1]));
}

// ---------------------------------------------------------------------------
// CSR construction
// ---------------------------------------------------------------------------
__global__ void zero_kernel(int* deg, int M) {
    int i = blockIdx.x * blockDim.x + threadIdx.x;
    if (i < M) deg[i] = 0;
}

__global__ void deg_count_kernel(const int* __restrict__ dst, int* deg, int E) {
    int i = (blockIdx.x * blockDim.x + threadIdx.x) * 4;
    if (i + 3 < E) {
        int4 d = *(const int4*)(dst + i);
        atomicAdd(&deg[d.x], 1);
        atomicAdd(&deg[d.y], 1);
        atomicAdd(&deg[d.z], 1);
        atomicAdd(&deg[d.w], 1);
    } else {
        for (int j = i; j < E; j++) atomicAdd(&deg[dst[j]], 1);
    }
}

__global__ void dinv_kernel(const int* __restrict__ deg, float* dinv, int M) {
    int i = blockIdx.x * blockDim.x + threadIdx.x;
    if (i < M) dinv[i] = rsqrtf((float)deg[i] + 1.0f);
}

__global__ __launch_bounds__(1024) void scan_block_kernel(
    const int* __restrict__ deg, int* row_ptr, int* bsum, int M)
{
    int gid  = blockIdx.x * 1024 + threadIdx.x;
    int lane = threadIdx.x & 31;
    int wid  = threadIdx.x >> 5;
    int v = (gid < M) ? deg[gid] : 0;
    int x = v;
    #pragma unroll
    for (int o = 1; o < 32; o <<= 1) {
        int t = __shfl_up_sync(0xffffffffu, x, o);
        if (lane >= o) x += t;
    }
    __shared__ int ws[32];
    if (lane == 31) ws[wid] = x;
    __syncthreads();
    if (wid == 0) {
        int y = ws[lane];
        #pragma unroll
        for (int o = 1; o < 32; o <<= 1) {
            int t = __shfl_up_sync(0xffffffffu, y, o);
            if (lane >= o) y += t;
        }
        ws[lane] = y;
    }
    __syncthreads();
    int base = (wid > 0) ? ws[wid - 1] : 0;
    int incl = base + x;
    if (gid < M) row_ptr[gid] = incl - v;
    if (threadIdx.x == 1023) bsum[blockIdx.x] = incl;
}

__global__ void scan_sums_kernel(int* bsum, int nb) {
    if (threadIdx.x == 0 && blockIdx.x == 0) {
        int acc = 0;
        for (int i = 0; i < nb; i++) { int t = bsum[i]; bsum[i] = acc; acc += t; }
    }
}

__global__ void add_offsets_kernel(int* row_ptr, int* cursor,
                                   const int* __restrict__ bsum, int M) {
    int gid = blockIdx.x * blockDim.x + threadIdx.x;
    if (gid < M) {
        int v = row_ptr[gid] + bsum[gid >> 10];
        row_ptr[gid] = v;
        cursor[gid]  = v;
    }
}

__global__ void bin_edges_kernel(const int* __restrict__ src, const int* __restrict__ dst,
                                 int* cursor, int* sorted_src, int E)
{
    int i = blockIdx.x * blockDim.x + threadIdx.x;
    if (i >= E) return;
    int pos = atomicAdd(&cursor[dst[i]], 1);
    sorted_src[pos] = src[i];
}

// ---------------------------------------------------------------------------
// W fragment prep: W[128k][128n] fp32 -> fp16 b-frags for mma.m16n8k16.
// element (k,n): na=n>>3, g=n&7, kb=k>>4, kk=k&15, q=(kk&7)>>1, reg=kk>>3, h=kk&1
// lane = g*4+q; halfslot index = (((na*8+kb)*32+lane)*2+reg)*2 + h
// ---------------------------------------------------------------------------
__global__ void wprep_kernel(const float* __restrict__ W, unsigned* Wf) {
    int idx = blockIdx.x * blockDim.x + threadIdx.x;
    if (idx >= 16384) return;
    int k = idx >> 7;
    int n = idx & 127;
    __half w = __float2half_rn(W[idx]);
    int na = n >> 3, g = n & 7;
    int kb = k >> 4, kk = k & 15;
    int q = (kk & 7) >> 1, reg = kk >> 3, h = kk & 1;
    int lane = g * 4 + q;
    __half* out = (__half*)Wf;
    out[(((na * 8 + kb) * 32 + lane) * 2 + reg) * 2 + h] = w;
}

// ---------------------------------------------------------------------------
// fp16 tensor-core GEMM: hs(half) = transform(A)[M,128] @ W[128,128] * dinv[row].
// Block 128 rows, 8 warps, warp grid 4(M)x2(N), warp tile 32x64.
// A staged into smem as packed fp16 a-frags; W frags streamed from gmem (L1).
// ---------------------------------------------------------------------------
__global__ __launch_bounds__(256, 2) void gemm_f16_kernel(
    const float* __restrict__ A, const unsigned* __restrict__ Wf,
    const float* __restrict__ dinv, const float* __restrict__ bias, int relu,
    __half* __restrict__ hs, int M)
{
    extern __shared__ unsigned As[];   // [ma(8)][kb(8)][lane(32)][reg(4)] = 8192 uints = 32KB

    const int tid  = threadIdx.x;
    const int lane = tid & 31;
    const int warp = tid >> 5;
    const int block_row = blockIdx.x * 128;

    // ---- stage A tile (fp32 -> fp16 frag order) ----
    #pragma unroll
    for (int it = 0; it < 16; it++) {
        int idx = it * 256 + tid;
        int m  = idx >> 5;           // row in tile
        int kq = idx & 31;           // float4 index along K
        int grow = block_row + m;
        float4 v = make_float4(0.f, 0.f, 0.f, 0.f);
        if (grow < M) {
            v = *(const float4*)(A + (size_t)grow * 128 + kq * 4);
            if (bias) {
                float s = __ldg(dinv + grow);
                float4 bb = *(const float4*)(bias + kq * 4);
                v.x = v.x * s + bb.x; v.y = v.y * s + bb.y;
                v.z = v.z * s + bb.z; v.w = v.w * s + bb.w;
                if (relu) {
                    v.x = fmaxf(v.x, 0.f); v.y = fmaxf(v.y, 0.f);
                    v.z = fmaxf(v.z, 0.f); v.w = fmaxf(v.w, 0.f);
                }
            }
        }
        unsigned u0 = pack_half2(v.x, v.y);
        unsigned u1 = pack_half2(v.z, v.w);

        int ma = m >> 4;
        int g  = m & 7;
        int hi = (m >> 3) & 1;
        int kb = kq >> 2;
        int kk = (kq & 3) * 4;           // 0,4,8,12
        int q  = (kk & 7) >> 1;          // 0 or 2
        int reg = hi + 2 * (kk >> 3);    // a-frag register index
        int base = ((ma * 8 + kb) * 32) * 4;
        int l0 = ((g * 4 + q)     + kb * 4) & 31;   // swizzled lanes
        int l1 = ((g * 4 + q + 1) + kb * 4) & 31;
        As[base + l0 * 4 + reg] = u0;
        As[base + l1 * 4 + reg] = u1;
    }
    __syncthreads();

    // ---- mainloop ----
    const int warp_m = warp >> 1;
    const int warp_n = warp & 1;

    float acc[2][8][4];
    #pragma unroll
    for (int i = 0; i < 2; i++)
        #pragma unroll
        for (int j = 0; j < 8; j++)
            #pragma unroll
            for (int r = 0; r < 4; r++) acc[i][j][r] = 0.0f;

    #pragma unroll
    for (int kb = 0; kb < 8; kb++) {
        int lane_s = (lane + kb * 4) & 31;
        unsigned a[2][4];
        #pragma unroll
        for (int i = 0; i < 2; i++) {
            int ma = warp_m * 2 + i;
            uint4 av = *(const uint4*)(As + ((ma * 8 + kb) * 32 + lane_s) * 4);
            a[i][0] = av.x; a[i][1] = av.y; a[i][2] = av.z; a[i][3] = av.w;
        }
        #pragma unroll
        for (int j = 0; j < 8; j++) {
            int na = warp_n * 8 + j;
            uint2 b2 = __ldg((const uint2*)(Wf + ((size_t)(na * 8 + kb) * 32 + lane) * 2));
            unsigned b[2] = {b2.x, b2.y};
            mma_f16(acc[0][j], a[0], b);
            mma_f16(acc[1][j], a[1], b);
        }
    }

    // ---- epilogue: scale rows by dinv, store fp16 ----
    int g  = lane >> 2;
    int qc = lane & 3;
    #pragma unroll
    for (int i = 0; i < 2; i++) {
        int r0 = block_row + warp_m * 32 + i * 16 + g;
        int r1 = r0 + 8;
        float s0 = (r0 < M) ? __ldg(dinv + r0) : 0.f;
        float s1 = (r1 < M) ? __ldg(dinv + r1) : 0.f;
        #pragma unroll
        for (int j = 0; j < 8; j++) {
            int col = warp_n * 64 + j * 8 + qc * 2;
            if (r0 < M) {
                unsigned u = pack_half2(acc[i][j][0] * s0, acc[i][j][1] * s0);
                *(unsigned*)(hs + (size_t)r0 * 128 + col) = u;
            }
            if (r1 < M) {
                unsigned u = pack_half2(acc[i][j][2] * s1, acc[i][j][3] * s1);
                *(unsigned*)(hs + (size_t)r1 * 128 + col) = u;
            }
        }
    }
}

// ---------------------------------------------------------------------------
// Atomic-free aggregation: one warp per dst node, fp16 gather, fp32 accumulate.
// ---------------------------------------------------------------------------
__global__ __launch_bounds__(256) void agg_kernel(
    const int* __restrict__ sorted_src, const int* __restrict__ row_ptr,
    const int* __restrict__ deg,
    const __half* __restrict__ hs, float* __restrict__ agg, int M)
{
    int node = (blockIdx.x * 256 + threadIdx.x) >> 5;
    int lane = threadIdx.x & 31;
    if (node >= M) return;

    int beg = __ldg(row_ptr + node);
    int cnt = __ldg(deg + node);

    const uint2* hsrow = (const uint2*)hs;   // 32 uint2 per row

    float4 acc;
    {
        uint2 v = __ldg(hsrow + (size_t)node * 32 + lane);
        float2 a = __half22float2(*(__half2*)&v.x);
        float2 b = __half22float2(*(__half2*)&v.y);
        acc = make_float4(a.x, a.y, b.x, b.y);
    }

    int e = 0;
    while (e < cnt) {
        int batch = min(32, cnt - e);
        int s = (lane < batch) ? __ldg(sorted_src + beg + e + lane) : 0;
        int j = 0;
        for (; j + 4 <= batch; j += 4) {
            int s0 = __shfl_sync(0xffffffffu, s, j + 0);
            int s1 = __shfl_sync(0xffffffffu, s, j + 1);
            int s2 = __shfl_sync(0xffffffffu, s, j + 2);
            int s3 = __shfl_sync(0xffffffffu, s, j + 3);
            uint2 v0 = __ldg(hsrow + (size_t)s0 * 32 + lane);
            uint2 v1 = __ldg(hsrow + (size_t)s1 * 32 + lane);
            uint2 v2 = __ldg(hsrow + (size_t)s2 * 32 + lane);
            uint2 v3 = __ldg(hsrow + (size_t)s3 * 32 + lane);
            float2 a0 = __half22float2(*(__half2*)&v0.x), b0 = __half22float2(*(__half2*)&v0.y);
            float2 a1 = __half22float2(*(__half2*)&v1.x), b1 = __half22float2(*(__half2*)&v1.y);
            float2 a2 = __half22float2(*(__half2*)&v2.x), b2 = __half22float2(*(__half2*)&v2.y);
            float2 a3 = __half22float2(*(__half2*)&v3.x), b3 = __half22float2(*(__half2*)&v3.y);
            acc.x += a0.x + a1.x + a2.x + a3.x;
            acc.y += a0.y + a1.y + a2.y + a3.y;
            acc.z += b0.x + b1.x + b2.x + b3.x;
            acc.w += b0.y + b1.y + b2.y + b3.y;
        }
        for (; j < batch; j++) {
            int sj = __shfl_sync(0xffffffffu, s, j);
            uint2 v = __ldg(hsrow + (size_t)sj * 32 + lane);
            float2 a = __half22float2(*(__half2*)&v.x);
            float2 b = __half22float2(*(__half2*)&v.y);
            acc.x += a.x; acc.y += a.y; acc.z += b.x; acc.w += b.y;
        }
        e += batch;
    }

    *((float4*)(agg + (size_t)node * 128) + lane) = acc;
}

// ---------------------------------------------------------------------------
// Output GEMM: out[M,40] = (A*dinv + b2) @ Wout + bout
// ---------------------------------------------------------------------------
__global__ __launch_bounds__(128) void gemm_out_kernel(
    const float* __restrict__ A, const float* __restrict__ W,
    const float* __restrict__ dinv, const float* __restrict__ bias2,
    const float* __restrict__ bout, float* __restrict__ out, int M)
{
    __shared__ float As2[128][64];
    __shared__ float Ws[128 * 40];

    const int rb  = blockIdx.x * 64;
    const int tid = threadIdx.x;

    for (int i = tid; i < 128 * 40; i += 128) Ws[i] = W[i];

    for (int i = tid; i < 64 * 32; i += 128) {
        int r  = i >> 5;
        int c4 = i & 31;
        int grow = rb + r;
        float4 v = make_float4(0.f, 0.f, 0.f, 0.f);
        if (grow < M) {
            v = *(const float4*)(A + (size_t)grow * 128 + c4 * 4);
            float s = __ldg(dinv + grow);
            float4 bb = *(const float4*)(bias2 + c4 * 4);
            v.x = v.x * s + bb.x; v.y = v.y * s + bb.y;
            v.z = v.z * s + bb.z; v.w = v.w * s + bb.w;
        }
        As2[c4 * 4 + 0][r] = v.x;
        As2[c4 * 4 + 1][r] = v.y;
        As2[c4 * 4 + 2][r] = v.z;
        As2[c4 * 4 + 3][r] = v.w;
    }
    __syncthreads();

    const int tcol = tid & 7;
    const int trow = tid >> 3;
    float acc[4][5];
    #pragma unroll
    for (int i = 0; i < 4; i++)
        #pragma unroll
        for (int j = 0; j < 5; j++) acc[i][j] = 0.0f;

    #pragma unroll 4
    for (int k = 0; k < 128; k++) {
        float a[4], w[5];
        #pragma unroll
        for (int i = 0; i < 4; i++) a[i] = As2[k][trow * 4 + i];
        #pragma unroll
        for (int j = 0; j < 5; j++) w[j] = Ws[k * 40 + tcol * 5 + j];
        #pragma unroll
        for (int i = 0; i < 4; i++)
            #pragma unroll
            for (int j = 0; j < 5; j++) acc[i][j] += a[i] * w[j];
    }

    #pragma unroll
    for (int i = 0; i < 4; i++) {
        int grow = rb + trow * 4 + i;
        if (grow >= M) break;
        #pragma unroll
        for (int j = 0; j < 5; j++) {
            int c = tcol * 5 + j;
            out[(size_t)grow * 40 + c] = acc[i][j] + __ldg(bout + c);
        }
    }
}

// ---------------------------------------------------------------------------

extern "C" void kernel_launch(void* const* d_in, const int* in_sizes, int n_in,
                              void* d_out, int out_size)
{
    const float* x    = (const float*)d_in[0];
    const int*   ei   = (const int*)d_in[1];
    const float* W1   = (const float*)d_in[2];
    const float* b1   = (const float*)d_in[3];
    const float* W2   = (const float*)d_in[4];
    const float* b2   = (const float*)d_in[5];
    const float* Wout = (const float*)d_in[6];
    const float* bout = (const float*)d_in[7];
    float* out = (float*)d_out;

    const int M = in_sizes[0] / FDIM;
    const int E = in_sizes[1] / 2;
    const int* src = ei;
    const int* dst = ei + E;

    __half* bufH;
    float *bufB, *dinv;
    unsigned *w1f, *w2f;
    int *deg, *cursor, *rowptr, *bsum, *srcsorted;
    cudaGetSymbolAddress((void**)&bufH, g_bufH);
    cudaGetSymbolAddress((void**)&bufB, g_bufB);
    cudaGetSymbolAddress((void**)&dinv, g_dinv);
    cudaGetSymbolAddress((void**)&deg, g_deg);
    cudaGetSymbolAddress((void**)&cursor, g_cursor);
    cudaGetSymbolAddress((void**)&rowptr, g_rowptr);
    cudaGetSymbolAddress((void**)&bsum, g_bsum);
    cudaGetSymbolAddress((void**)&srcsorted, g_srcsorted);
    cudaGetSymbolAddress((void**)&w1f, g_W1f);
    cudaGetSymbolAddress((void**)&w2f, g_W2f);

    static int smem_set = 0;
    if (!smem_set) {
        cudaFuncSetAttribute(gemm_f16_kernel,
                             cudaFuncAttributeMaxDynamicSharedMemorySize, 32768);
        smem_set = 1;
    }

    const int nb_nodes = (M + 255) / 256;
    const int nb_edges = (E + 255) / 256;
    const int nb_edge4 = (E + 1023) / 1024;
    const int nb_scan  = (M + 1023) / 1024;
    const int nb_gemm  = (M + 127) / 128;
    const int nb_agg   = (M + 7) / 8;
    const int nb_gout  = (M + 63) / 64;

    // --- W fragment prep + CSR build + dinv ---
    wprep_kernel<<<64, 256>>>(W1, w1f);
    wprep_kernel<<<64, 256>>>(W2, w2f);
    zero_kernel<<<nb_nodes, 256>>>(deg, M);
    deg_count_kernel<<<nb_edge4, 256>>>(dst, deg, E);
    dinv_kernel<<<nb_nodes, 256>>>(deg, dinv, M);
    scan_block_kernel<<<nb_scan, 1024>>>(deg, rowptr, bsum, M);
    scan_sums_kernel<<<1, 32>>>(bsum, nb_scan);
    add_offsets_kernel<<<nb_nodes, 256>>>(rowptr, cursor, bsum, M);
    bin_edges_kernel<<<nb_edges, 256>>>(src, dst, cursor, srcsorted, E);

    // --- Layer 1: hs1 -> bufH (fp16); agg1 -> bufB (fp32) ---
    gemm_f16_kernel<<<nb_gemm, 256, 32768>>>(x, w1f, dinv, nullptr, 0, bufH, M);
    agg_kernel<<<nb_agg, 256>>>(srcsorted, rowptr, deg, bufH, bufB, M);

    // --- Layer 2: relu(agg1*dinv+b1) fused into A-load; hs2 -> bufH ---
    gemm_f16_kernel<<<nb_gemm, 256, 32768>>>(bufB, w2f, dinv, b1, 1, bufH, M);
    agg_kernel<<<nb_agg, 256>>>(srcsorted, rowptr, deg, bufH, bufB, M);

    // --- Output: h2 = agg2*dinv + b2 fused; out = h2 @ Wout + bout ---
    gemm_out_kernel<<<nb_gout, 128>>>(bufB, Wout, dinv, b2, bout, out, M);
}